// round 2
// baseline (speedup 1.0000x reference)
#include <cuda_runtime.h>
#include <math.h>

// Petrosian fractal features, 5 scales, T=4096, 57 windows/row.
// One block per (b,c) row. Row loaded once into smem; sign-change
// indicator prefix-summed; each window = 2 prefix lookups.

#define T_LEN 4096
#define THREADS 256
#define PER_THREAD 16   // 4096 / 256
#define N_WIN 57

__global__ __launch_bounds__(THREADS)
void petrosian_kernel(const float* __restrict__ x, float* __restrict__ out, int n_rows) {
    __shared__ float row[T_LEN];
    __shared__ int   pre[T_LEN];
    __shared__ int   warp_sums[8];

    const int bc = blockIdx.x;
    if (bc >= n_rows) return;
    const float* xr = x + (size_t)bc * T_LEN;
    const int tid = threadIdx.x;

    // ---- load row (coalesced float4) ----
    const float4* x4 = (const float4*)xr;
    float4* r4 = (float4*)row;
    #pragma unroll
    for (int i = 0; i < 4; i++)
        r4[tid + i * THREADS] = x4[tid + i * THREADS];
    __syncthreads();

    // ---- indicator + local inclusive scan over 16 consecutive j ----
    // s[j] = (row[j+1]-row[j])*(row[j+2]-row[j+1]) < 0, valid j in [0, T-3]
    int vals[PER_THREAD];
    const int base = tid * PER_THREAD;
    float a  = row[base];
    float b  = row[base + 1];
    float d0 = b - a;
    int local = 0;
    #pragma unroll
    for (int i = 0; i < PER_THREAD; i++) {
        int j = base + i;
        float c_ = (j + 2 < T_LEN) ? row[j + 2] : 0.0f;
        float d1 = c_ - b;
        int s = (j + 2 < T_LEN) && (d0 * d1 < 0.0f);
        local += s;
        vals[i] = local;
        b = c_;
        d0 = d1;
    }

    // ---- warp scan of per-thread totals ----
    const int lane = tid & 31, wid = tid >> 5;
    int scan = local;
    #pragma unroll
    for (int off = 1; off < 32; off <<= 1) {
        int n = __shfl_up_sync(0xffffffffu, scan, off);
        if (lane >= off) scan += n;
    }
    if (lane == 31) warp_sums[wid] = scan;
    __syncthreads();

    // exclusive scan of the 8 warp totals (warp 0, lanes 0..7)
    if (wid == 0 && lane < 8) {
        int v = warp_sums[lane];
        int sc = v;
        #pragma unroll
        for (int off = 1; off < 8; off <<= 1) {
            int n = __shfl_up_sync(0xffu, sc, off);
            if (lane >= off) sc += n;
        }
        warp_sums[lane] = sc - v;   // exclusive
    }
    __syncthreads();

    const int thread_excl = warp_sums[wid] + (scan - local);
    #pragma unroll
    for (int i = 0; i < PER_THREAD; i++)
        pre[base + i] = thread_excl + vals[i];  // inclusive global prefix
    __syncthreads();

    // ---- 57 window outputs: zc = pre[start+w-3] - pre[start-1] ----
    if (tid < N_WIN) {
        int k = tid, w, start;
        if      (k < 1)  { w = 4096; start = 0; }
        else if (k < 4)  { w = 2048; start = (k - 1)  * 1024; }
        else if (k < 11) { w = 1024; start = (k - 4)  * 512;  }
        else if (k < 26) { w = 512;  start = (k - 11) * 256;  }
        else             { w = 256;  start = (k - 26) * 128;  }

        int hi = pre[start + w - 3];
        int lo = (start > 0) ? pre[start - 1] : 0;
        float zc = (float)(hi - lo);

        float wf = (float)w;
        float L = log10f(wf);
        float denom = L + log10f(wf / (wf + 0.4f * zc));
        out[(size_t)bc * N_WIN + k] = L / denom;
    }
}

extern "C" void kernel_launch(void* const* d_in, const int* in_sizes, int n_in,
                              void* d_out, int out_size) {
    const float* x = (const float*)d_in[0];
    float* out = (float*)d_out;
    int n_rows = in_sizes[0] / T_LEN;   // B*C = 4096
    petrosian_kernel<<<n_rows, THREADS>>>(x, out, n_rows);
}

// round 3
// speedup vs baseline: 1.0010x; 1.0010x over previous
#include <cuda_runtime.h>
#include <math.h>

// Petrosian fractal features, 5 scales, T=4096, 57 windows/row.
// One block per (b,c) row. Row loaded once into smem; sign-change
// indicator prefix-summed; each window = 2 prefix lookups.

#define T_LEN 4096
#define THREADS 256
#define PER_THREAD 16   // 4096 / 256
#define N_WIN 57

__global__ __launch_bounds__(THREADS)
void petrosian_kernel(const float* __restrict__ x, float* __restrict__ out, int n_rows) {
    __shared__ float row[T_LEN];
    __shared__ int   pre[T_LEN];
    __shared__ int   warp_sums[8];

    const int bc = blockIdx.x;
    if (bc >= n_rows) return;
    const float* xr = x + (size_t)bc * T_LEN;
    const int tid = threadIdx.x;

    // ---- load row (coalesced float4) ----
    const float4* x4 = (const float4*)xr;
    float4* r4 = (float4*)row;
    #pragma unroll
    for (int i = 0; i < 4; i++)
        r4[tid + i * THREADS] = x4[tid + i * THREADS];
    __syncthreads();

    // ---- indicator + local inclusive scan over 16 consecutive j ----
    // s[j] = (row[j+1]-row[j])*(row[j+2]-row[j+1]) < 0, valid j in [0, T-3]
    int vals[PER_THREAD];
    const int base = tid * PER_THREAD;
    float a  = row[base];
    float b  = row[base + 1];
    float d0 = b - a;
    int local = 0;
    #pragma unroll
    for (int i = 0; i < PER_THREAD; i++) {
        int j = base + i;
        float c_ = (j + 2 < T_LEN) ? row[j + 2] : 0.0f;
        float d1 = c_ - b;
        int s = (j + 2 < T_LEN) && (d0 * d1 < 0.0f);
        local += s;
        vals[i] = local;
        b = c_;
        d0 = d1;
    }

    // ---- warp scan of per-thread totals ----
    const int lane = tid & 31, wid = tid >> 5;
    int scan = local;
    #pragma unroll
    for (int off = 1; off < 32; off <<= 1) {
        int n = __shfl_up_sync(0xffffffffu, scan, off);
        if (lane >= off) scan += n;
    }
    if (lane == 31) warp_sums[wid] = scan;
    __syncthreads();

    // exclusive scan of the 8 warp totals (warp 0, lanes 0..7)
    if (wid == 0 && lane < 8) {
        int v = warp_sums[lane];
        int sc = v;
        #pragma unroll
        for (int off = 1; off < 8; off <<= 1) {
            int n = __shfl_up_sync(0xffu, sc, off);
            if (lane >= off) sc += n;
        }
        warp_sums[lane] = sc - v;   // exclusive
    }
    __syncthreads();

    const int thread_excl = warp_sums[wid] + (scan - local);
    #pragma unroll
    for (int i = 0; i < PER_THREAD; i++)
        pre[base + i] = thread_excl + vals[i];  // inclusive global prefix
    __syncthreads();

    // ---- 57 window outputs: zc = pre[start+w-3] - pre[start-1] ----
    if (tid < N_WIN) {
        int k = tid, w, start;
        if      (k < 1)  { w = 4096; start = 0; }
        else if (k < 4)  { w = 2048; start = (k - 1)  * 1024; }
        else if (k < 11) { w = 1024; start = (k - 4)  * 512;  }
        else if (k < 26) { w = 512;  start = (k - 11) * 256;  }
        else             { w = 256;  start = (k - 26) * 128;  }

        int hi = pre[start + w - 3];
        int lo = (start > 0) ? pre[start - 1] : 0;
        float zc = (float)(hi - lo);

        float wf = (float)w;
        float L = log10f(wf);
        float denom = L + log10f(wf / (wf + 0.4f * zc));
        out[(size_t)bc * N_WIN + k] = L / denom;
    }
}

extern "C" void kernel_launch(void* const* d_in, const int* in_sizes, int n_in,
                              void* d_out, int out_size) {
    const float* x = (const float*)d_in[0];
    float* out = (float*)d_out;
    int n_rows = in_sizes[0] / T_LEN;   // B*C = 4096
    petrosian_kernel<<<n_rows, THREADS>>>(x, out, n_rows);
}

// round 4
// speedup vs baseline: 1.8617x; 1.8598x over previous
#include <cuda_runtime.h>
#include <math.h>

// Petrosian fractal features, 5 scales, T=4096, 57 windows/row.
// One block per (b,c) row. Registers-only data path: each thread owns 16
// contiguous elements; only 33 segment prefixes + boundary corrections go
// through (tiny) shared memory. All window boundaries are multiples of 128:
//   zc(window [128a, 128b)) = S[b] - S[a] - s[128b-2] - s[128b-1]
// where S[m] = sum of s[0 .. 128m-1], s[j] = sign-change indicator.

#define T_LEN   4096
#define THREADS 256
#define PT      16     // elements per thread
#define NSEG    32     // 128-element segments per row
#define N_WIN   57

__global__ __launch_bounds__(THREADS)
void petrosian_kernel(const float* __restrict__ x, float* __restrict__ out) {
    __shared__ int warp_tot[8];
    __shared__ int segS[NSEG + 1];   // segS[m] = prefix of s through index 128m-1
    __shared__ int bcorr[NSEG + 1];  // s[128m-2] + s[128m-1]

    const int bc  = blockIdx.x;
    const float* xr = x + (size_t)bc * T_LEN;
    const int tid  = threadIdx.x;
    const int base = tid * PT;

    // ---- load 16 contiguous elements + 2-element halo into registers ----
    float v[PT + 2];
    const float4* x4 = (const float4*)(xr + base);
    #pragma unroll
    for (int i = 0; i < 4; i++) {
        float4 t = x4[i];
        v[4*i+0] = t.x; v[4*i+1] = t.y; v[4*i+2] = t.z; v[4*i+3] = t.w;
    }
    if (tid < THREADS - 1) {
        float2 h = *(const float2*)(xr + base + PT);
        v[PT] = h.x; v[PT+1] = h.y;
    } else {
        v[PT] = 0.0f; v[PT+1] = 0.0f;   // never used as valid s (j > T-3)
    }

    // ---- indicator bits s[base+i], i = 0..15 (valid while base+i <= T-3) ----
    int cnt = 0, s14 = 0, s15 = 0;
    float dprev = v[1] - v[0];
    #pragma unroll
    for (int i = 0; i < PT; i++) {
        float dn = v[i+2] - v[i+1];
        int s = (dprev * dn < 0.0f) ? 1 : 0;
        if (i >= PT - 2 && tid == THREADS - 1) s = 0;  // j = 4094, 4095 invalid
        cnt += s;
        if (i == PT - 2) s14 = s;
        if (i == PT - 1) s15 = s;
        dprev = dn;
    }

    // ---- warp inclusive scan of per-thread counts ----
    const int lane = tid & 31, wid = tid >> 5;
    int scan = cnt;
    #pragma unroll
    for (int off = 1; off < 32; off <<= 1) {
        int n = __shfl_up_sync(0xffffffffu, scan, off);
        if (lane >= off) scan += n;
    }
    if (lane == 31) warp_tot[wid] = scan;
    // boundary correction for segment boundary m = (tid+1)/8 (tid % 8 == 7)
    if ((tid & 7) == 7) bcorr[(tid >> 3) + 1] = s14 + s15;  // bcorr[32] = 0 naturally
    __syncthreads();

    // ---- exclusive scan of 8 warp totals (trivial, thread 0) ----
    if (tid == 0) {
        int acc = 0;
        #pragma unroll
        for (int m = 0; m < 8; m++) { int t = warp_tot[m]; warp_tot[m] = acc; acc += t; }
        segS[0] = 0; bcorr[0] = 0;
    }
    __syncthreads();

    // ---- publish segment prefixes: thread 8m-1 holds inclusive through 128m-1
    if ((tid & 7) == 7) segS[(tid >> 3) + 1] = warp_tot[wid] + scan;
    __syncthreads();

    // ---- 57 window outputs ----
    if (tid < N_WIN) {
        int k = tid, w, a;
        if      (k < 1)  { w = 4096; a = 0; }
        else if (k < 4)  { w = 2048; a = (k - 1)  * 8; }
        else if (k < 11) { w = 1024; a = (k - 4)  * 4; }
        else if (k < 26) { w = 512;  a = (k - 11) * 2; }
        else             { w = 256;  a = (k - 26); }
        int b = a + w / 128;

        float zc = (float)(segS[b] - segS[a] - bcorr[b]);
        float wf = (float)w;
        float L  = log10f(wf);
        float denom = L + log10f(wf / (wf + 0.4f * zc));
        out[(size_t)bc * N_WIN + k] = L / denom;
    }
}

extern "C" void kernel_launch(void* const* d_in, const int* in_sizes, int n_in,
                              void* d_out, int out_size) {
    const float* x = (const float*)d_in[0];
    float* out = (float*)d_out;
    int n_rows = in_sizes[0] / T_LEN;   // B*C = 4096
    petrosian_kernel<<<n_rows, THREADS>>>(x, out);
}

// round 5
// speedup vs baseline: 2.1231x; 1.1404x over previous
#include <cuda_runtime.h>
#include <math.h>

// Petrosian fractal features, 5 scales, T=4096, 57 windows/row.
// One block per (b,c) row. Pure-register data path: each thread owns 16
// contiguous elements (4x LDG.128, nothing else from global). The 2-element
// halo comes from the neighbor lane via shfl_down (+ a 64B smem exchange at
// warp boundaries). Segment sums (128-elem segments = 8 threads) via
// __reduce_add_sync; one 32-wide scan in warp 0 gives all window prefixes:
//   zc(window [128a,128b)) = S[b] - S[a] - s[128b-2] - s[128b-1]

#define T_LEN   4096
#define THREADS 256
#define PT      16
#define NSEG    32
#define N_WIN   57

__global__ __launch_bounds__(THREADS)
void petrosian_kernel(const float* __restrict__ x, float* __restrict__ out) {
    __shared__ float halo[8][2];      // v[0], v[1] of lane 0 of each warp
    __shared__ int   segsum[NSEG];    // per-128-segment indicator sums
    __shared__ int   segS[NSEG + 1];  // prefix through 128m-1
    __shared__ int   bcorr[NSEG + 1]; // s[128m-2] + s[128m-1]

    const int bc   = blockIdx.x;
    const float* xr = x + (size_t)bc * T_LEN;
    const int tid  = threadIdx.x;
    const int lane = tid & 31, wid = tid >> 5;
    const int base = tid * PT;

    // ---- 16 contiguous elements, registers only ----
    float v[PT];
    const float4* x4 = (const float4*)(xr + base);
    #pragma unroll
    for (int i = 0; i < 4; i++) {
        float4 t = x4[i];
        v[4*i+0] = t.x; v[4*i+1] = t.y; v[4*i+2] = t.z; v[4*i+3] = t.w;
    }

    // halo candidates from next lane (lane 31 fixed up after the barrier)
    float h0 = __shfl_down_sync(0xffffffffu, v[0], 1);
    float h1 = __shfl_down_sync(0xffffffffu, v[1], 1);
    if (lane == 0) { halo[wid][0] = v[0]; halo[wid][1] = v[1]; }

    // ---- bulk indicators i = 0..13 (self-contained in v[0..15]) ----
    int cnt = 0;
    float dp = v[1] - v[0];
    #pragma unroll
    for (int i = 0; i < PT - 2; i++) {
        float dn = v[i+2] - v[i+1];
        cnt += (dp * dn < 0.0f) ? 1 : 0;
        dp = dn;
    }

    __syncthreads();   // halo[] visible

    if (lane == 31) {
        int nw = wid + 1;
        h0 = (nw < 8) ? halo[nw][0] : 0.0f;
        h1 = (nw < 8) ? halo[nw][1] : 0.0f;
    }

    // ---- last two indicators (j = base+14, base+15) ----
    float d14 = h0 - v[15];
    float d15 = h1 - h0;
    int s14 = (dp  * d14 < 0.0f) && (tid != THREADS - 1);
    int s15 = (d14 * d15 < 0.0f) && (tid != THREADS - 1);
    cnt += s14 + s15;

    // ---- 8-lane segment sum (segment = 8 consecutive threads = 128 elems) ----
    unsigned gmask = 0xFFu << (lane & 24);
    int ssum = __reduce_add_sync(gmask, cnt);
    if ((tid & 7) == 7) {
        segsum[tid >> 3] = ssum;
        bcorr[(tid >> 3) + 1] = s14 + s15;   // bcorr[32] = 0 via forced s=0
    }
    __syncthreads();

    // ---- warp 0: inclusive scan of 32 segment sums ----
    if (wid == 0) {
        int sc = segsum[lane];
        #pragma unroll
        for (int off = 1; off < 32; off <<= 1) {
            int n = __shfl_up_sync(0xffffffffu, sc, off);
            if (lane >= off) sc += n;
        }
        segS[lane + 1] = sc;
        if (lane == 0) segS[0] = 0;
    }
    __syncthreads();

    // ---- 57 window outputs ----
    if (tid < N_WIN) {
        int k = tid, w, a;
        if      (k < 1)  { w = 4096; a = 0; }
        else if (k < 4)  { w = 2048; a = (k - 1)  * 8; }
        else if (k < 11) { w = 1024; a = (k - 4)  * 4; }
        else if (k < 26) { w = 512;  a = (k - 11) * 2; }
        else             { w = 256;  a = (k - 26); }
        int b = a + w / 128;

        float zc = (float)(segS[b] - segS[a] - bcorr[b]);
        float wf = (float)w;
        float L  = log10f(wf);
        float denom = L + log10f(wf / (wf + 0.4f * zc));
        out[(size_t)bc * N_WIN + k] = L / denom;
    }
}

extern "C" void kernel_launch(void* const* d_in, const int* in_sizes, int n_in,
                              void* d_out, int out_size) {
    const float* x = (const float*)d_in[0];
    float* out = (float*)d_out;
    int n_rows = in_sizes[0] / T_LEN;   // B*C = 4096
    petrosian_kernel<<<n_rows, THREADS>>>(x, out);
}